// round 1
// baseline (speedup 1.0000x reference)
#include <cuda_runtime.h>

// Problem constants
#define BB  4
#define NN  2048
#define DD  256
#define HH  8
#define DKK 32
#define INV_SCALE 0.17677669529663687f   // 1/sqrt(32)

// Scratch (device globals; allocation-free per harness rules)
__device__ float g_Q [BB*HH*NN*DKK];   // [b][h][n][dk]
__device__ float g_K [BB*HH*NN*DKK];
__device__ float g_V [BB*HH*NN*DKK];
__device__ float g_AO[BB*NN*DD];       // [b][n][h*DK+dk] == [row][d]

// ---------------------------------------------------------------------------
// Kernel 1: QKV projection.  Y = X @ W^T, written in head-split layout.
// grid = (128, 4, 3), block = 256. 64x64 tile, BK=32, 4x4 per thread.
// ---------------------------------------------------------------------------
__global__ __launch_bounds__(256) void qkv_kernel(
    const float* __restrict__ X,
    const float* __restrict__ Wq,
    const float* __restrict__ Wk,
    const float* __restrict__ Wv)
{
    __shared__ float Xs[64][33];
    __shared__ float Ws[64][33];

    const float* W = (blockIdx.z == 0) ? Wq : (blockIdx.z == 1) ? Wk : Wv;
    float*       Y = (blockIdx.z == 0) ? g_Q : (blockIdx.z == 1) ? g_K : g_V;

    const int row0 = blockIdx.x * 64;
    const int col0 = blockIdx.y * 64;
    const int t  = threadIdx.x;
    const int ti = t >> 4, tj = t & 15;
    const int i0 = ti * 4, j0 = tj * 4;

    float acc[4][4];
#pragma unroll
    for (int r = 0; r < 4; r++)
#pragma unroll
        for (int c = 0; c < 4; c++) acc[r][c] = 0.f;

    for (int k0 = 0; k0 < DD; k0 += 32) {
        __syncthreads();
        for (int idx = t; idx < 64 * 32; idx += 256) {
            int r = idx >> 5, k = idx & 31;
            Xs[r][k] = X[(row0 + r) * DD + k0 + k];
            Ws[r][k] = W[(col0 + r) * DD + k0 + k];
        }
        __syncthreads();
#pragma unroll
        for (int k = 0; k < 32; k++) {
            float a0 = Xs[i0+0][k], a1 = Xs[i0+1][k], a2 = Xs[i0+2][k], a3 = Xs[i0+3][k];
            float b0 = Ws[j0+0][k], b1 = Ws[j0+1][k], b2 = Ws[j0+2][k], b3 = Ws[j0+3][k];
            acc[0][0] = fmaf(a0,b0,acc[0][0]); acc[0][1] = fmaf(a0,b1,acc[0][1]);
            acc[0][2] = fmaf(a0,b2,acc[0][2]); acc[0][3] = fmaf(a0,b3,acc[0][3]);
            acc[1][0] = fmaf(a1,b0,acc[1][0]); acc[1][1] = fmaf(a1,b1,acc[1][1]);
            acc[1][2] = fmaf(a1,b2,acc[1][2]); acc[1][3] = fmaf(a1,b3,acc[1][3]);
            acc[2][0] = fmaf(a2,b0,acc[2][0]); acc[2][1] = fmaf(a2,b1,acc[2][1]);
            acc[2][2] = fmaf(a2,b2,acc[2][2]); acc[2][3] = fmaf(a2,b3,acc[2][3]);
            acc[3][0] = fmaf(a3,b0,acc[3][0]); acc[3][1] = fmaf(a3,b1,acc[3][1]);
            acc[3][2] = fmaf(a3,b2,acc[3][2]); acc[3][3] = fmaf(a3,b3,acc[3][3]);
        }
    }

#pragma unroll
    for (int r = 0; r < 4; r++) {
        int rg = row0 + i0 + r;
        int b  = rg >> 11;           // rg / 2048
        int n  = rg & (NN - 1);
#pragma unroll
        for (int c = 0; c < 4; c++) {
            int cg = col0 + j0 + c;
            int h  = cg >> 5;
            int dk = cg & 31;
            Y[(((b * HH + h) * NN) + n) * DKK + dk] = acc[r][c];
        }
    }
}

// ---------------------------------------------------------------------------
// Kernel 2: fused attention (scores + edge + mask + online softmax + PV).
// One block per (b*H+h, q-tile of 64). 256 threads: 16x16 thread grid,
// each thread owns a 4x4 tile of S and 4 rows x 2 dk-cols of O.
// ---------------------------------------------------------------------------
__global__ __launch_bounds__(256) void attn_kernel(
    const float* __restrict__ edge,
    const int*   __restrict__ mask)
{
    __shared__ float Qs[64][DKK + 1];
    __shared__ float Ks[64][DKK + 1];
    __shared__ float Vs[64][DKK + 1];
    __shared__ float Ps[64][65];

    const int bh = blockIdx.y;          // 0..31
    const int b  = bh >> 3;
    const int h  = bh & 7;
    const int q0 = blockIdx.x * 64;

    const float* Qp = g_Q + (size_t)bh * NN * DKK;
    const float* Kp = g_K + (size_t)bh * NN * DKK;
    const float* Vp = g_V + (size_t)bh * NN * DKK;

    const int t  = threadIdx.x;
    const int ti = t >> 4, tj = t & 15;
    const int i0 = ti * 4, j0 = tj * 4;
    const int dk0 = tj * 2;

    for (int idx = t; idx < 64 * DKK; idx += 256) {
        int r = idx >> 5, k = idx & 31;
        Qs[r][k] = Qp[(q0 + r) * DKK + k];
    }

    float mrow[4], lrow[4], acc0[4], acc1[4];
#pragma unroll
    for (int r = 0; r < 4; r++) { mrow[r] = -1e30f; lrow[r] = 0.f; acc0[r] = 0.f; acc1[r] = 0.f; }

    for (int m0 = 0; m0 < NN; m0 += 64) {
        __syncthreads();   // previous iter's Ps/Vs reads done
        for (int idx = t; idx < 64 * DKK; idx += 256) {
            int r = idx >> 5, k = idx & 31;
            Ks[r][k] = Kp[(m0 + r) * DKK + k];
            Vs[r][k] = Vp[(m0 + r) * DKK + k];
        }
        __syncthreads();

        // S = Q K^T  (4x4 per thread)
        float s[4][4];
#pragma unroll
        for (int r = 0; r < 4; r++)
#pragma unroll
            for (int c = 0; c < 4; c++) s[r][c] = 0.f;

#pragma unroll
        for (int k = 0; k < DKK; k++) {
            float a0 = Qs[i0+0][k], a1 = Qs[i0+1][k], a2 = Qs[i0+2][k], a3 = Qs[i0+3][k];
            float b0 = Ks[j0+0][k], b1 = Ks[j0+1][k], b2 = Ks[j0+2][k], b3 = Ks[j0+3][k];
            s[0][0] = fmaf(a0,b0,s[0][0]); s[0][1] = fmaf(a0,b1,s[0][1]);
            s[0][2] = fmaf(a0,b2,s[0][2]); s[0][3] = fmaf(a0,b3,s[0][3]);
            s[1][0] = fmaf(a1,b0,s[1][0]); s[1][1] = fmaf(a1,b1,s[1][1]);
            s[1][2] = fmaf(a1,b2,s[1][2]); s[1][3] = fmaf(a1,b3,s[1][3]);
            s[2][0] = fmaf(a2,b0,s[2][0]); s[2][1] = fmaf(a2,b1,s[2][1]);
            s[2][2] = fmaf(a2,b2,s[2][2]); s[2][3] = fmaf(a2,b3,s[2][3]);
            s[3][0] = fmaf(a3,b0,s[3][0]); s[3][1] = fmaf(a3,b1,s[3][1]);
            s[3][2] = fmaf(a3,b2,s[3][2]); s[3][3] = fmaf(a3,b3,s[3][3]);
        }

        // scale + edge bias + mask  (vectorized 16B loads, coalesced)
#pragma unroll
        for (int r = 0; r < 4; r++) {
            int base = ((b * NN) + q0 + i0 + r) * NN + m0 + j0;
            float4 e = *reinterpret_cast<const float4*>(edge + base);
            int4  mk = *reinterpret_cast<const int4*>(mask + base);
            s[r][0] = mk.x ? fmaf(s[r][0], INV_SCALE, e.x) : -1e9f;
            s[r][1] = mk.y ? fmaf(s[r][1], INV_SCALE, e.y) : -1e9f;
            s[r][2] = mk.z ? fmaf(s[r][2], INV_SCALE, e.z) : -1e9f;
            s[r][3] = mk.w ? fmaf(s[r][3], INV_SCALE, e.w) : -1e9f;
        }

        // online softmax: row groups are 16 consecutive lanes (shfl-xor reduce)
#pragma unroll
        for (int r = 0; r < 4; r++) {
            float mx = fmaxf(fmaxf(s[r][0], s[r][1]), fmaxf(s[r][2], s[r][3]));
            mx = fmaxf(mx, __shfl_xor_sync(0xffffffffu, mx, 1));
            mx = fmaxf(mx, __shfl_xor_sync(0xffffffffu, mx, 2));
            mx = fmaxf(mx, __shfl_xor_sync(0xffffffffu, mx, 4));
            mx = fmaxf(mx, __shfl_xor_sync(0xffffffffu, mx, 8));
            float mn   = fmaxf(mrow[r], mx);
            float corr = __expf(mrow[r] - mn);
            mrow[r] = mn;
            float p0 = __expf(s[r][0] - mn);
            float p1 = __expf(s[r][1] - mn);
            float p2 = __expf(s[r][2] - mn);
            float p3 = __expf(s[r][3] - mn);
            float rs = (p0 + p1) + (p2 + p3);
            rs += __shfl_xor_sync(0xffffffffu, rs, 1);
            rs += __shfl_xor_sync(0xffffffffu, rs, 2);
            rs += __shfl_xor_sync(0xffffffffu, rs, 4);
            rs += __shfl_xor_sync(0xffffffffu, rs, 8);
            lrow[r] = lrow[r] * corr + rs;
            acc0[r] *= corr;
            acc1[r] *= corr;
            Ps[i0 + r][j0 + 0] = p0;
            Ps[i0 + r][j0 + 1] = p1;
            Ps[i0 + r][j0 + 2] = p2;
            Ps[i0 + r][j0 + 3] = p3;
        }
        __syncthreads();

        // O += P V   (each thread: 4 rows x 2 dk columns)
#pragma unroll 8
        for (int j = 0; j < 64; j++) {
            float v0 = Vs[j][dk0];
            float v1 = Vs[j][dk0 + 1];
#pragma unroll
            for (int r = 0; r < 4; r++) {
                float p = Ps[i0 + r][j];
                acc0[r] = fmaf(p, v0, acc0[r]);
                acc1[r] = fmaf(p, v1, acc1[r]);
            }
        }
    }

#pragma unroll
    for (int r = 0; r < 4; r++) {
        float invl = 1.0f / lrow[r];
        int n = q0 + i0 + r;
        int o = ((b * NN) + n) * DD + h * DKK + dk0;
        g_AO[o]     = acc0[r] * invl;
        g_AO[o + 1] = acc1[r] * invl;
    }
}

// ---------------------------------------------------------------------------
// Kernel 3: output projection.  out = AO @ Wo^T + bo
// ---------------------------------------------------------------------------
__global__ __launch_bounds__(256) void proj_kernel(
    const float* __restrict__ Wo,
    const float* __restrict__ bo,
    float* __restrict__ out)
{
    __shared__ float Xs[64][33];
    __shared__ float Ws[64][33];

    const int row0 = blockIdx.x * 64;
    const int col0 = blockIdx.y * 64;
    const int t  = threadIdx.x;
    const int ti = t >> 4, tj = t & 15;
    const int i0 = ti * 4, j0 = tj * 4;

    float acc[4][4];
#pragma unroll
    for (int r = 0; r < 4; r++)
#pragma unroll
        for (int c = 0; c < 4; c++) acc[r][c] = 0.f;

    for (int k0 = 0; k0 < DD; k0 += 32) {
        __syncthreads();
        for (int idx = t; idx < 64 * 32; idx += 256) {
            int r = idx >> 5, k = idx & 31;
            Xs[r][k] = g_AO[(row0 + r) * DD + k0 + k];
            Ws[r][k] = Wo[(col0 + r) * DD + k0 + k];
        }
        __syncthreads();
#pragma unroll
        for (int k = 0; k < 32; k++) {
            float a0 = Xs[i0+0][k], a1 = Xs[i0+1][k], a2 = Xs[i0+2][k], a3 = Xs[i0+3][k];
            float b0 = Ws[j0+0][k], b1 = Ws[j0+1][k], b2 = Ws[j0+2][k], b3 = Ws[j0+3][k];
            acc[0][0] = fmaf(a0,b0,acc[0][0]); acc[0][1] = fmaf(a0,b1,acc[0][1]);
            acc[0][2] = fmaf(a0,b2,acc[0][2]); acc[0][3] = fmaf(a0,b3,acc[0][3]);
            acc[1][0] = fmaf(a1,b0,acc[1][0]); acc[1][1] = fmaf(a1,b1,acc[1][1]);
            acc[1][2] = fmaf(a1,b2,acc[1][2]); acc[1][3] = fmaf(a1,b3,acc[1][3]);
            acc[2][0] = fmaf(a2,b0,acc[2][0]); acc[2][1] = fmaf(a2,b1,acc[2][1]);
            acc[2][2] = fmaf(a2,b2,acc[2][2]); acc[2][3] = fmaf(a2,b3,acc[2][3]);
            acc[3][0] = fmaf(a3,b0,acc[3][0]); acc[3][1] = fmaf(a3,b1,acc[3][1]);
            acc[3][2] = fmaf(a3,b2,acc[3][2]); acc[3][3] = fmaf(a3,b3,acc[3][3]);
        }
    }

#pragma unroll
    for (int r = 0; r < 4; r++) {
        int rg = row0 + i0 + r;
#pragma unroll
        for (int c = 0; c < 4; c++) {
            int cg = col0 + j0 + c;
            out[rg * DD + cg] = acc[r][c] + bo[cg];
        }
    }
}

// ---------------------------------------------------------------------------
extern "C" void kernel_launch(void* const* d_in, const int* in_sizes, int n_in,
                              void* d_out, int out_size)
{
    const float* x    = (const float*)d_in[0];
    const float* edge = (const float*)d_in[1];
    const int*   mask = (const int*)  d_in[2];
    const float* wq   = (const float*)d_in[3];
    const float* wk   = (const float*)d_in[4];
    const float* wv   = (const float*)d_in[5];
    const float* wo   = (const float*)d_in[6];
    const float* bo   = (const float*)d_in[7];
    float* out = (float*)d_out;

    dim3 g1((BB * NN) / 64, DD / 64, 3);
    qkv_kernel<<<g1, 256>>>(x, wq, wk, wv);

    dim3 g2(NN / 64, BB * HH);
    attn_kernel<<<g2, 256>>>(edge, mask);

    dim3 g3((BB * NN) / 64, DD / 64);
    proj_kernel<<<g3, 256>>>(wo, bo, out);
}